// round 15
// baseline (speedup 1.0000x reference)
#include <cuda_runtime.h>

// Problem shape (fixed by reference setup_inputs)
#define NBATCH 2
#define DD 160
#define HH 192
#define WW 224
#define HHWW (HH * WW)

// Tiling — R11 champion config + minBlocks=7 (force regs <= 36 for 56 warps/SM)
#define TX 32
#define TY 16
#define TZ 32
#define YPT 2                   // blockDim.y = 8
#define NTHREADS 256
#define HROWS 18
#define HCOLS 34
#define HALO_ELEMS (HROWS * HCOLS)   // 612
#define SBUF 768                     // padded: 3 unconditional 256-thread stores
#define GXB 7
#define GYB 12
#define GZB (NBATCH * (DD / TZ))     // 10
#define TOTAL_BLOCKS (GXB * GYB * GZB)  // 840

__device__ double g_partial[TOTAL_BLOCKS];
__device__ unsigned int g_count = 0;    // self-wrapping via atomicInc

__device__ __forceinline__ void load_plane(
    const float* __restrict__ xp, const float* __restrict__ yp,
    const bool ok[3], const int off[3], bool zok, float* v)
{
#pragma unroll
    for (int i = 0; i < 3; ++i) {
        const bool o = zok && ok[i];
        const float a = o ? __ldg(xp + off[i]) : 0.f;
        const float b = o ? __ldg(yp + off[i]) : 0.f;
        v[i] = a - b;
    }
}

__device__ __forceinline__ void store_plane(float* sbuf, int tid, const float* v)
{
    sbuf[tid]       = v[0];
    sbuf[tid + 256] = v[1];
    sbuf[tid + 512] = v[2];   // padded buffer: always in range
}

__device__ __forceinline__ void compute_plane(
    const float* sbuf, int rowbase, float A[YPT], float B[YPT], float C[YPT])
{
    float rsx[YPT + 2], rdx[YPT + 2];
#pragma unroll
    for (int k = 0; k < YPT + 2; ++k) {
        const float* row = sbuf + rowbase + k * HCOLS;
        const float dm = row[-1];
        const float d0 = row[0];
        const float dp = row[1];
        rsx[k] = fmaf(2.f, d0, dm + dp);
        rdx[k] = dm - dp;
    }
#pragma unroll
    for (int j = 0; j < YPT; ++j) {
        A[j] = fmaf(2.f, rsx[j + 1], rsx[j] + rsx[j + 2]);
        C[j] = rsx[j] - rsx[j + 2];
        B[j] = fmaf(2.f, rdx[j + 1], rdx[j] + rdx[j + 2]);
    }
}

__device__ __forceinline__ void emit_shift(
    const float A[YPT], const float B[YPT], const float C[YPT],
    float A2[YPT], float A1[YPT], float B2[YPT], float B1[YPT],
    float C2[YPT], float C1[YPT], float& acc)
{
#pragma unroll
    for (int j = 0; j < YPT; ++j) {
        const float fx = A2[j] - A[j];                      // diff_z
        const float fy = fmaf(2.f, C1[j], C2[j] + C[j]);    // smooth_z
        const float fz = fmaf(2.f, B1[j], B2[j] + B[j]);    // smooth_z
        acc = fmaf(fx, fx, acc);
        acc = fmaf(fy, fy, acc);
        acc = fmaf(fz, fz, acc);
        A2[j] = A1[j]; A1[j] = A[j];
        B2[j] = B1[j]; B1[j] = B[j];
        C2[j] = C1[j]; C1[j] = C[j];
    }
}

__global__ void __launch_bounds__(NTHREADS, 7) grad_loss_kernel(
    const float* __restrict__ x, const float* __restrict__ y,
    float* __restrict__ out)
{
    __shared__ float sd[4][SBUF];   // 4-deep ring of padded (x-y) planes

    const int tx  = threadIdx.x;
    const int ty  = threadIdx.y;
    const int tid = ty * 32 + tx;

    const int x0 = blockIdx.x * TX;
    const int y0 = blockIdx.y * TY;
    const int bz = blockIdx.z;
    const int n  = bz / (DD / TZ);
    const int z0 = (bz % (DD / TZ)) * TZ;
    const int bid = blockIdx.x + GXB * (blockIdx.y + GYB * blockIdx.z);

    // ---- plane-invariant halo-load bookkeeping ----
    int  off[3];
    bool ok[3];
#pragma unroll
    for (int i = 0; i < 3; ++i) {
        const int idx = tid + i * NTHREADS;
        const int r   = idx / HCOLS;
        const int c   = idx - r * HCOLS;
        const int gy  = y0 - 1 + r;
        const int gx  = x0 - 1 + c;
        const bool v  = (idx < HALO_ELEMS) &&
                        (gy >= 0) && (gy < HH) && (gx >= 0) && (gx < WW);
        ok[i]  = v;
        off[i] = v ? (gy * WW + gx) : 0;
    }

    // Rolling plane pointers (bumped per plane; clamped start)
    const size_t nbase = (size_t)n * DD * HHWW;
    const int zst = (z0 > 0) ? (z0 - 1) : 0;
    const float* xp = x + nbase + (size_t)zst * HHWW;
    const float* yp = y + nbase + (size_t)zst * HHWW;

    const int rowbase = (ty * YPT) * HCOLS + (tx + 1);

    float A2[YPT], A1[YPT], B2[YPT], B1[YPT], C2[YPT], C1[YPT];
    float acc = 0.f;
    float v0[3], v1[3];
    float A[YPT], B[YPT], C[YPT];

    // ---- prologue: planes q=0 (gz=z0-1, zero-pad if z0==0) and q=1 (gz=z0) ----
    load_plane(xp, yp, ok, off, z0 > 0, v0);
    if (z0 > 0) { xp += HHWW; yp += HHWW; }       // now at plane z0
    load_plane(xp, yp, ok, off, true, v1);
    xp += HHWW; yp += HHWW;                       // now at plane z0+1 (q=2)
    store_plane(&sd[0][0], tid, v0);
    store_plane(&sd[1][0], tid, v1);
    __syncthreads();

    // ---- warm-up step s=1: load q=2,3; compute q=0 -> state2, q=1 -> state1 ----
    load_plane(xp, yp, ok, off, true, v0);  xp += HHWW; yp += HHWW;
    load_plane(xp, yp, ok, off, true, v1);  xp += HHWW; yp += HHWW;
    compute_plane(&sd[0][0], rowbase, A2, B2, C2);
    compute_plane(&sd[1][0], rowbase, A1, B1, C1);
    store_plane(&sd[2][0], tid, v0);
    store_plane(&sd[3][0], tid, v1);
    __syncthreads();

    // ---- main loop s=2..15: load q=2s,2s+1 (interior, valid); compute+emit q=2s-2,2s-1 ----
#pragma unroll 2
    for (int s = 2; s <= 15; ++s) {
        load_plane(xp, yp, ok, off, true, v0);  xp += HHWW; yp += HHWW;
        load_plane(xp, yp, ok, off, true, v1);  xp += HHWW; yp += HHWW;

        compute_plane(&sd[(2 * s - 2) & 3][0], rowbase, A, B, C);
        emit_shift(A, B, C, A2, A1, B2, B1, C2, C1, acc);
        compute_plane(&sd[(2 * s - 1) & 3][0], rowbase, A, B, C);
        emit_shift(A, B, C, A2, A1, B2, B1, C2, C1, acc);

        store_plane(&sd[(2 * s) & 3][0], tid, v0);
        store_plane(&sd[(2 * s + 1) & 3][0], tid, v1);
        __syncthreads();
    }

    // ---- peeled s=16: load q=32 (gz=z0+31, valid), q=33 (gz=z0+32, maybe OOB) ----
    {
        load_plane(xp, yp, ok, off, true, v0);  xp += HHWW; yp += HHWW;
        load_plane(xp, yp, ok, off, z0 + TZ < DD, v1);

        compute_plane(&sd[30 & 3][0], rowbase, A, B, C);   // q=30 -> buf2
        emit_shift(A, B, C, A2, A1, B2, B1, C2, C1, acc);
        compute_plane(&sd[31 & 3][0], rowbase, A, B, C);   // q=31 -> buf3
        emit_shift(A, B, C, A2, A1, B2, B1, C2, C1, acc);

        store_plane(&sd[32 & 3][0], tid, v0);              // buf0
        store_plane(&sd[33 & 3][0], tid, v1);              // buf1
        __syncthreads();
    }

    // ---- tail: compute+emit q=32, q=33 (no load, no store) ----
    compute_plane(&sd[0][0], rowbase, A, B, C);
    emit_shift(A, B, C, A2, A1, B2, B1, C2, C1, acc);
    compute_plane(&sd[1][0], rowbase, A, B, C);
    emit_shift(A, B, C, A2, A1, B2, B1, C2, C1, acc);

    // ---- block reduction (deterministic order) ----
#pragma unroll
    for (int o = 16; o; o >>= 1)
        acc += __shfl_down_sync(0xffffffffu, acc, o);

    __shared__ float warpsum[8];
    __shared__ bool  s_last;
    if (tx == 0) warpsum[ty] = acc;
    __syncthreads();
    if (tid == 0) {
        float s = 0.f;
#pragma unroll
        for (int w = 0; w < 8; ++w) s += warpsum[w];
        g_partial[bid] = (double)s;
        __threadfence();
        const unsigned old = atomicInc(&g_count, TOTAL_BLOCKS - 1); // wraps to 0
        s_last = (old == TOTAL_BLOCKS - 1);
    }
    __syncthreads();

    // ---- last block: sum partials, write scalar output ----
    if (s_last) {
        double ds = 0.0;
        for (int i = tid; i < TOTAL_BLOCKS; i += NTHREADS)
            ds += g_partial[i];
#pragma unroll
        for (int o = 16; o; o >>= 1)
            ds += __shfl_down_sync(0xffffffffu, ds, o);
        __shared__ double dwarp[8];
        if (tx == 0) dwarp[ty] = ds;
        __syncthreads();
        if (tid == 0) {
            double t = 0.0;
#pragma unroll
            for (int w = 0; w < 8; ++w) t += dwarp[w];
            out[0] = (float)(t / ((double)NBATCH * DD * HH * WW));
        }
    }
}

extern "C" void kernel_launch(void* const* d_in, const int* in_sizes, int n_in,
                              void* d_out, int out_size)
{
    const float* x = (const float*)d_in[0];
    const float* y = (const float*)d_in[1];
    float* out = (float*)d_out;

    dim3 block(32, TY / YPT, 1);     // 256 threads
    dim3 grid(GXB, GYB, GZB);        // 7 x 12 x 10 = 840
    grad_loss_kernel<<<grid, block>>>(x, y, out);
}

// round 16
// speedup vs baseline: 1.2654x; 1.2654x over previous
#include <cuda_runtime.h>

// Problem shape (fixed by reference setup_inputs)
#define NBATCH 2
#define DD 160
#define HH 192
#define WW 224
#define HHWW (HH * WW)

// Tiling — R11 champion skeleton + all-or-nothing float2 halo loads
#define TX 32
#define TY 16
#define TZ 32
#define YPT 2                   // blockDim.y = 8
#define NTHREADS 256
#define HROWS 18
#define HCOLS 36                // floats per smem row: [x0-2, x0+34), even-aligned
#define F2ROW 18                // float2 per row
#define HALO_F2 (HROWS * F2ROW) // 324 float2 per plane
#define SBUF2 512               // float2 per buffer (2 * 256) — stores unconditional
#define GXB 7
#define GYB 12
#define GZB (NBATCH * (DD / TZ))     // 10
#define TOTAL_BLOCKS (GXB * GYB * GZB)  // 840

__device__ double g_partial[TOTAL_BLOCKS];
__device__ unsigned int g_count = 0;    // self-wrapping via atomicInc

__device__ __forceinline__ void load_plane(
    const float* __restrict__ xp, const float* __restrict__ yp,
    const bool ok[2], const int off[2], bool zok, float2* v)
{
#pragma unroll
    for (int i = 0; i < 2; ++i) {
        const bool o = zok && ok[i];
        float2 a = o ? *(const float2*)(xp + off[i]) : make_float2(0.f, 0.f);
        float2 b = o ? *(const float2*)(yp + off[i]) : make_float2(0.f, 0.f);
        v[i] = make_float2(a.x - b.x, a.y - b.y);
    }
}

__device__ __forceinline__ void store_plane(float2* sbuf, int tid, const float2* v)
{
    sbuf[tid]       = v[0];
    sbuf[tid + 256] = v[1];     // SBUF2 == 512: always in range
}

__device__ __forceinline__ void compute_plane(
    const float2* sbuf2, int rowbase, float A[YPT], float B[YPT], float C[YPT])
{
    const float* sbuf = (const float*)sbuf2;
    float rsx[YPT + 2], rdx[YPT + 2];
#pragma unroll
    for (int k = 0; k < YPT + 2; ++k) {
        const float* row = sbuf + rowbase + k * HCOLS;
        const float dm = row[-1];
        const float d0 = row[0];
        const float dp = row[1];
        rsx[k] = fmaf(2.f, d0, dm + dp);
        rdx[k] = dm - dp;
    }
#pragma unroll
    for (int j = 0; j < YPT; ++j) {
        A[j] = fmaf(2.f, rsx[j + 1], rsx[j] + rsx[j + 2]);
        C[j] = rsx[j] - rsx[j + 2];
        B[j] = fmaf(2.f, rdx[j + 1], rdx[j] + rdx[j + 2]);
    }
}

__device__ __forceinline__ void emit_shift(
    const float A[YPT], const float B[YPT], const float C[YPT],
    float A2[YPT], float A1[YPT], float B2[YPT], float B1[YPT],
    float C2[YPT], float C1[YPT], float& acc)
{
#pragma unroll
    for (int j = 0; j < YPT; ++j) {
        const float fx = A2[j] - A[j];                      // diff_z
        const float fy = fmaf(2.f, C1[j], C2[j] + C[j]);    // smooth_z
        const float fz = fmaf(2.f, B1[j], B2[j] + B[j]);    // smooth_z
        acc = fmaf(fx, fx, acc);
        acc = fmaf(fy, fy, acc);
        acc = fmaf(fz, fz, acc);
        A2[j] = A1[j]; A1[j] = A[j];
        B2[j] = B1[j]; B1[j] = B[j];
        C2[j] = C1[j]; C1[j] = C[j];
    }
}

__global__ void __launch_bounds__(NTHREADS) grad_loss_kernel(
    const float* __restrict__ x, const float* __restrict__ y,
    float* __restrict__ out)
{
    __shared__ float2 sd[4][SBUF2];   // 4-deep ring of padded (x-y) planes

    const int tx  = threadIdx.x;
    const int ty  = threadIdx.y;
    const int tid = ty * 32 + tx;

    const int x0 = blockIdx.x * TX;
    const int y0 = blockIdx.y * TY;
    const int bz = blockIdx.z;
    const int n  = bz / (DD / TZ);
    const int z0 = (bz % (DD / TZ)) * TZ;
    const int bid = blockIdx.x + GXB * (blockIdx.y + GYB * blockIdx.z);

    // ---- plane-invariant halo-load bookkeeping (all-or-nothing float2) ----
    int  off[2];
    bool ok[2];
#pragma unroll
    for (int i = 0; i < 2; ++i) {
        const int idx = tid + i * NTHREADS;          // float2 index
        const int r   = idx / F2ROW;
        const int c   = idx - r * F2ROW;
        const int gy  = y0 - 1 + r;
        const int gx2 = x0 - 2 + 2 * c;              // even -> 8B aligned
        const bool v  = (idx < HALO_F2) &&
                        (gy >= 0) && (gy < HH) && (gx2 >= 0) && (gx2 + 1 < WW);
        ok[i]  = v;
        off[i] = v ? (gy * WW + gx2) : 0;
    }

    // Rolling plane pointers (bumped per plane; clamped start)
    const size_t nbase = (size_t)n * DD * HHWW;
    const int zst = (z0 > 0) ? (z0 - 1) : 0;
    const float* xp = x + nbase + (size_t)zst * HHWW;
    const float* yp = y + nbase + (size_t)zst * HHWW;

    // output pixel x0+tx sits at smem col tx+2 (col0 == x0-2)
    const int rowbase = (ty * YPT) * HCOLS + (tx + 2);

    float A2[YPT], A1[YPT], B2[YPT], B1[YPT], C2[YPT], C1[YPT];
    float acc = 0.f;
    float2 v0[2], v1[2];
    float A[YPT], B[YPT], C[YPT];

    // ---- prologue: planes q=0 (gz=z0-1, zero-pad if z0==0) and q=1 (gz=z0) ----
    load_plane(xp, yp, ok, off, z0 > 0, v0);
    if (z0 > 0) { xp += HHWW; yp += HHWW; }       // now at plane z0
    load_plane(xp, yp, ok, off, true, v1);
    xp += HHWW; yp += HHWW;                       // now at plane z0+1 (q=2)
    store_plane(&sd[0][0], tid, v0);
    store_plane(&sd[1][0], tid, v1);
    __syncthreads();

    // ---- warm-up step s=1: load q=2,3; compute q=0 -> state2, q=1 -> state1 ----
    load_plane(xp, yp, ok, off, true, v0);  xp += HHWW; yp += HHWW;
    load_plane(xp, yp, ok, off, true, v1);  xp += HHWW; yp += HHWW;
    compute_plane(&sd[0][0], rowbase, A2, B2, C2);
    compute_plane(&sd[1][0], rowbase, A1, B1, C1);
    store_plane(&sd[2][0], tid, v0);
    store_plane(&sd[3][0], tid, v1);
    __syncthreads();

    // ---- main loop s=2..15: load q=2s,2s+1 (interior, valid); compute+emit q=2s-2,2s-1 ----
#pragma unroll 2
    for (int s = 2; s <= 15; ++s) {
        load_plane(xp, yp, ok, off, true, v0);  xp += HHWW; yp += HHWW;
        load_plane(xp, yp, ok, off, true, v1);  xp += HHWW; yp += HHWW;

        compute_plane(&sd[(2 * s - 2) & 3][0], rowbase, A, B, C);
        emit_shift(A, B, C, A2, A1, B2, B1, C2, C1, acc);
        compute_plane(&sd[(2 * s - 1) & 3][0], rowbase, A, B, C);
        emit_shift(A, B, C, A2, A1, B2, B1, C2, C1, acc);

        store_plane(&sd[(2 * s) & 3][0], tid, v0);
        store_plane(&sd[(2 * s + 1) & 3][0], tid, v1);
        __syncthreads();
    }

    // ---- peeled s=16: load q=32 (gz=z0+31, valid), q=33 (gz=z0+32, maybe OOB) ----
    {
        load_plane(xp, yp, ok, off, true, v0);  xp += HHWW; yp += HHWW;
        load_plane(xp, yp, ok, off, z0 + TZ < DD, v1);

        compute_plane(&sd[30 & 3][0], rowbase, A, B, C);   // q=30 -> buf2
        emit_shift(A, B, C, A2, A1, B2, B1, C2, C1, acc);
        compute_plane(&sd[31 & 3][0], rowbase, A, B, C);   // q=31 -> buf3
        emit_shift(A, B, C, A2, A1, B2, B1, C2, C1, acc);

        store_plane(&sd[32 & 3][0], tid, v0);              // buf0
        store_plane(&sd[33 & 3][0], tid, v1);              // buf1
        __syncthreads();
    }

    // ---- tail: compute+emit q=32, q=33 (no load, no store) ----
    compute_plane(&sd[0][0], rowbase, A, B, C);
    emit_shift(A, B, C, A2, A1, B2, B1, C2, C1, acc);
    compute_plane(&sd[1][0], rowbase, A, B, C);
    emit_shift(A, B, C, A2, A1, B2, B1, C2, C1, acc);

    // ---- block reduction (deterministic order) ----
#pragma unroll
    for (int o = 16; o; o >>= 1)
        acc += __shfl_down_sync(0xffffffffu, acc, o);

    __shared__ float warpsum[8];
    __shared__ bool  s_last;
    if (tx == 0) warpsum[ty] = acc;
    __syncthreads();
    if (tid == 0) {
        float s = 0.f;
#pragma unroll
        for (int w = 0; w < 8; ++w) s += warpsum[w];
        g_partial[bid] = (double)s;
        __threadfence();
        const unsigned old = atomicInc(&g_count, TOTAL_BLOCKS - 1); // wraps to 0
        s_last = (old == TOTAL_BLOCKS - 1);
    }
    __syncthreads();

    // ---- last block: sum partials, write scalar output ----
    if (s_last) {
        double ds = 0.0;
        for (int i = tid; i < TOTAL_BLOCKS; i += NTHREADS)
            ds += g_partial[i];
#pragma unroll
        for (int o = 16; o; o >>= 1)
            ds += __shfl_down_sync(0xffffffffu, ds, o);
        __shared__ double dwarp[8];
        if (tx == 0) dwarp[ty] = ds;
        __syncthreads();
        if (tid == 0) {
            double t = 0.0;
#pragma unroll
            for (int w = 0; w < 8; ++w) t += dwarp[w];
            out[0] = (float)(t / ((double)NBATCH * DD * HH * WW));
        }
    }
}

extern "C" void kernel_launch(void* const* d_in, const int* in_sizes, int n_in,
                              void* d_out, int out_size)
{
    const float* x = (const float*)d_in[0];
    const float* y = (const float*)d_in[1];
    float* out = (float*)d_out;

    dim3 block(32, TY / YPT, 1);     // 256 threads
    dim3 grid(GXB, GYB, GZB);        // 7 x 12 x 10 = 840
    grad_loss_kernel<<<grid, block>>>(x, y, out);
}